// round 13
// baseline (speedup 1.0000x reference)
#include <cuda_runtime.h>
#include <cuda_pipeline.h>
#include <cuda_bf16.h>
#include <math.h>
#include <stdint.h>
#include <mma.h>

using namespace nvcuda;

// Problem constants (fixed by the reference)
#define B_  8
#define L_  1024
#define D_  512
#define V_  64
#define K_  8
#define L2_ 2048            // masks are (B, 2L)
#define INV_TEMP 10.0f
#define EPSF 1e-10f
#define KCH 64              // k-chunk per pipeline stage (4 x k16 mma steps)
#define KPAD 72             // padded row stride in halfs (144 B)
#define NSTAGE 2
#define STAGE_ELEMS (2 * 128 * KPAD)              // bf16 elems per stage (A+B)
#define GEMM_DYN_SMEM (NSTAGE * STAGE_ELEMS * 2)  // 73728 bytes

// -------- deterministic scratch (device globals; no allocations) --------
__device__ __nv_bfloat16 g_boxH[B_ * L_ * D_];   // bf16 box_proj (8 MB)
__device__ __nv_bfloat16 g_tagH[B_ * L_ * D_];   // bf16 tag_proj (8 MB)
__device__ float g_den_part[B_ * L_ * 8];    // [b*L+l][t_tile(128-wide)] masked exp partial sums
__device__ float g_cls_S[1024];
__device__ float g_cls_C[1024];
__device__ float g_emp_S[1024];              // [b*128 + chunk]
__device__ float g_emp_C[1024];
__device__ float g_ptr_S[1024];
__device__ float g_ptr_C[1024];
__device__ float g_con_L[2 * B_ * L_];       // [slot][b*L+i]
__device__ float g_con_P[2 * B_ * L_];

// ---- inline mask-mode probe: attention_mask[:, :L] is guaranteed all-True ----
// word 0 of att: 1 -> int32 masks, 0x3F800000 -> float32, else packed bytes.
__device__ __forceinline__ int mask_mode_of(const void* att) {
    unsigned int w = *(const unsigned int*)att;
    if (w == 1u) return 1;
    if (w == 0x3F800000u) return 2;
    return 0;
}

__device__ __forceinline__ int mask_at(const void* p, int idx, int mode) {
    if (mode == 1) return ((const int*)p)[idx] != 0;
    if (mode == 2) return ((const float*)p)[idx] != 0.0f;
    return ((const unsigned char*)p)[idx] != 0;
}

// ======================= fp32 -> bf16 convert pass (+ fused empty-BCE) =======================
// grid 2048: blocks [0,1024) convert box (flat). Blocks [1024,2048): convert tag,
// warp-per-row, AND compute the empty-pointer BCE dot inline (saves re-reading tag_proj).
__global__ void __launch_bounds__(256) k_cvt(const float* __restrict__ boxp,
                                             const float* __restrict__ tagp,
                                             const float* __restrict__ emp,
                                             const void* __restrict__ att,
                                             const void* __restrict__ dtm) {
    int blk = blockIdx.x;
    if (blk < 1024) {
        size_t base = ((size_t)blk * 256 + threadIdx.x) * 16;
        const float4* s = (const float4*)(boxp + base);
        __nv_bfloat162* d = (__nv_bfloat162*)(g_boxH + base);
        float4 v0 = s[0], v1 = s[1], v2 = s[2], v3 = s[3];   // batch loads (MLP 4)
        d[0] = __floats2bfloat162_rn(v0.x, v0.y); d[1] = __floats2bfloat162_rn(v0.z, v0.w);
        d[2] = __floats2bfloat162_rn(v1.x, v1.y); d[3] = __floats2bfloat162_rn(v1.z, v1.w);
        d[4] = __floats2bfloat162_rn(v2.x, v2.y); d[5] = __floats2bfloat162_rn(v2.z, v2.w);
        d[6] = __floats2bfloat162_rn(v3.x, v3.y); d[7] = __floats2bfloat162_rn(v3.z, v3.w);
        return;
    }
    // tag half: 8 warps, warp per row (8 rows per block)
    int mode = mask_mode_of(att);
    int bt = blk - 1024;                     // 0..1023
    int warp = threadIdx.x >> 5, lane = threadIdx.x & 31;
    int row = bt * 8 + warp;                 // = b*L + t
    int b = row >> 10, t = row & 1023;
    const float4* tp4 = (const float4*)(tagp + (size_t)row * D_);
    const float4* ep4 = (const float4*)(emp + (size_t)b * D_);
    __nv_bfloat162* dp = (__nv_bfloat162*)(g_tagH + (size_t)row * D_);
    float acc = 0.f;
    #pragma unroll
    for (int i = 0; i < 4; i++) {
        int idx = lane + 32 * i;             // float4 index within row
        float4 v = tp4[idx];
        float4 e = ep4[idx];
        acc += v.x * e.x + v.y * e.y + v.z * e.z + v.w * e.w;
        dp[2 * idx]     = __floats2bfloat162_rn(v.x, v.y);
        dp[2 * idx + 1] = __floats2bfloat162_rn(v.z, v.w);
    }
    #pragma unroll
    for (int o = 16; o; o >>= 1) acc += __shfl_xor_sync(0xffffffffu, acc, o);
    int a = mask_at(att, b * L2_ + L_ + t, mode);
    int d = mask_at(dtm, b * L2_ + L_ + t, mode);
    float tgt = (a && !d) ? 1.f : 0.f;
    float el = acc;
    float bce = fmaxf(el, 0.f) + log1pf(__expf(-fabsf(el))) - el * tgt;
    __shared__ float sS[8], sC[8];
    if (lane == 0) { sS[warp] = a ? bce : 0.f; sC[warp] = (float)a; }
    __syncthreads();
    if (threadIdx.x == 0) {
        float s = 0.f, c = 0.f;
        #pragma unroll
        for (int i = 0; i < 8; i++) { s += sS[i]; c += sC[i]; }
        g_emp_S[bt] = s; g_emp_C[bt] = c;
    }
}

// ======================= cls loss =======================
__global__ void __launch_bounds__(256) k_cls(const float* __restrict__ logits,
                                             const int* __restrict__ tok) {
    int warp = threadIdx.x >> 5, lane = threadIdx.x & 31;
    int row = blockIdx.x * 8 + warp;
    const float* p = logits + (size_t)row * V_;
    float s0 = p[lane], s1 = p[lane + 32];
    float m = fmaxf(s0, s1);
    #pragma unroll
    for (int o = 16; o; o >>= 1) m = fmaxf(m, __shfl_xor_sync(0xffffffffu, m, o));
    float e = __expf(s0 - m) + __expf(s1 - m);
    float ss = s0 + s1;
    int t = tok[row];
    float st = (lane == t ? s0 : 0.f) + (lane + 32 == t ? s1 : 0.f);
    #pragma unroll
    for (int o = 16; o; o >>= 1) {
        e  += __shfl_xor_sync(0xffffffffu, e, o);
        ss += __shfl_xor_sync(0xffffffffu, ss, o);
        st += __shfl_xor_sync(0xffffffffu, st, o);
    }
    float lse = m + logf(e);
    float per = 0.9f * (lse - st) + 0.1f * (lse - ss * (1.0f / V_));
    float valid = (t > 3) ? 1.f : 0.f;   // SPECIAL_IDS = 0..3
    __shared__ float sS[8], sC[8];
    if (lane == 0) { sS[warp] = per * valid; sC[warp] = valid; }
    __syncthreads();
    if (threadIdx.x == 0) {
        float a = 0.f, c = 0.f;
        #pragma unroll
        for (int i = 0; i < 8; i++) { a += sS[i]; c += sC[i]; }
        g_cls_S[blockIdx.x] = a; g_cls_C[blockIdx.x] = c;
    }
}

// ======================= wmma bf16 GEMM + masked exp-sum (2-stage, KCH=64) =======================
__global__ void __launch_bounds__(256, 2) k_gemm(const void* __restrict__ att,
                                                 const void* __restrict__ dtm) {
    extern __shared__ __nv_bfloat16 dyn[];   // NSTAGE stages of [A|B][128][KPAD]
    __shared__ float red[128][2];
    __shared__ unsigned char sdtm[128];

    int mode = mask_mode_of(att);
    int b = blockIdx.z, lt = blockIdx.y, tt = blockIdx.x;
    int tid = threadIdx.x;
    int wid = tid >> 5, lane = tid & 31;
    int wm = wid >> 1, wn = wid & 1;     // 4 x 2 warp grid

    if (tid < 128) sdtm[tid] = (unsigned char)mask_at(dtm, b * L2_ + L_ + tt * 128 + tid, mode);

    const __nv_bfloat16* A  = g_boxH + (size_t)(b * L_ + lt * 128) * D_;
    const __nv_bfloat16* Bt = g_tagH + (size_t)(b * L_ + tt * 128) * D_;

    wmma::fragment<wmma::accumulator, 16, 16, 16, float> acc[2][4];
    #pragma unroll
    for (int mi = 0; mi < 2; mi++)
        #pragma unroll
        for (int ni = 0; ni < 4; ni++)
            wmma::fill_fragment(acc[mi][ni], 0.0f);

    auto prefetch = [&](int s, int kc) {
        __nv_bfloat16* stA = dyn + s * STAGE_ELEMS;
        __nv_bfloat16* stB = stA + 128 * KPAD;
        #pragma unroll
        for (int it = 0; it < 4; it++) {
            int a = tid + it * 256;              // 0..1023
            int r = a >> 3, c8 = (a & 7) * 8;    // 8 chunks of 8 halfs per row
            __pipeline_memcpy_async(&stA[r * KPAD + c8], A + (size_t)r * D_ + kc + c8, 16);
        }
        #pragma unroll
        for (int it = 0; it < 4; it++) {
            int a = tid + it * 256;
            int r = a >> 3, c8 = (a & 7) * 8;
            __pipeline_memcpy_async(&stB[r * KPAD + c8], Bt + (size_t)r * D_ + kc + c8, 16);
        }
        __pipeline_commit();
    };

    const int NIT = D_ / KCH;            // 8
    prefetch(0, 0);
    for (int i = 0; i < NIT; i++) {
        if (i + 1 < NIT) prefetch((i + 1) & 1, (i + 1) * KCH);
        __pipeline_wait_prior((i + 1 < NIT) ? 1 : 0);
        __syncthreads();
        __nv_bfloat16* stA = dyn + (i & 1) * STAGE_ELEMS;
        __nv_bfloat16* stB = stA + 128 * KPAD;
        #pragma unroll
        for (int kk = 0; kk < KCH; kk += 16) {
            wmma::fragment<wmma::matrix_a, 16, 16, 16, __nv_bfloat16, wmma::row_major> af[2];
            #pragma unroll
            for (int mi = 0; mi < 2; mi++)
                wmma::load_matrix_sync(af[mi], &stA[(wm * 32 + mi * 16) * KPAD + kk], KPAD);
            wmma::fragment<wmma::matrix_b, 16, 16, 16, __nv_bfloat16, wmma::col_major> bf[4];
            #pragma unroll
            for (int ni = 0; ni < 4; ni++)
                wmma::load_matrix_sync(bf[ni], &stB[(wn * 64 + ni * 16) * KPAD + kk], KPAD);
            #pragma unroll
            for (int mi = 0; mi < 2; mi++)
                #pragma unroll
                for (int ni = 0; ni < 4; ni++)
                    wmma::mma_sync(acc[mi][ni], af[mi], bf[ni], acc[mi][ni]);
        }
        __syncthreads();
    }

    // epilogue: masked exp + row reduce; per-warp fp32 scratch aliased onto dyn
    float* scr = (float*)dyn + wid * (16 * 20);   // 1280B/warp slice
    int r = lane & 15, h = lane >> 4;    // row within frag, column half
    #pragma unroll
    for (int mi = 0; mi < 2; mi++) {
        float rowsum = 0.f;
        #pragma unroll
        for (int ni = 0; ni < 4; ni++) {
            wmma::store_matrix_sync(scr, acc[mi][ni], 20, wmma::mem_row_major);
            __syncwarp();
            float s = 0.f;
            #pragma unroll
            for (int c = 0; c < 8; c++) {
                int col = h * 8 + c;
                int gc = wn * 64 + ni * 16 + col;
                if (sdtm[gc]) s += __expf(scr[r * 20 + col] * INV_TEMP);
            }
            rowsum += s;
            __syncwarp();
        }
        rowsum += __shfl_xor_sync(0xffffffffu, rowsum, 16);
        if (h == 0) red[wm * 32 + mi * 16 + r][wn] = rowsum;
    }
    __syncthreads();
    if (tid < 128) {
        float s = red[tid][0] + red[tid][1];
        g_den_part[(size_t)(b * L_ + lt * 128 + tid) * 8 + tt] = s;
    }
}

// ======================= pointer loss (targets + combine) =======================
__global__ void __launch_bounds__(256) k_ptr(const float* __restrict__ box,
                                             const float* __restrict__ tag,
                                             const int* __restrict__ bidx,
                                             const void* __restrict__ att,
                                             const void* __restrict__ dtm) {
    int mode = mask_mode_of(att);
    int warp = threadIdx.x >> 5, lane = threadIdx.x & 31;
    int gw = blockIdx.x * 8 + warp;          // gw = b*L + l
    int b = gw >> 10;
    float dv = (lane < 8) ? g_den_part[(size_t)gw * 8 + lane] : 0.f;
    #pragma unroll
    for (int o = 16; o; o >>= 1) dv += __shfl_xor_sync(0xffffffffu, dv, o);
    float logden = logf(dv + EPSF);
    const int* bi = bidx + (size_t)gw * K_;
    const float* brow = box + (size_t)gw * D_;
    float ts = 0.f, tc = 0.f;
    bool valid = true;
    for (int k = 0; k < K_; k++) {
        int idx = bi[k];
        if (idx < 0) valid = false;
        if (valid) {
            int rc = idx - L_;
            rc = rc < 0 ? 0 : (rc > L_ - 1 ? L_ - 1 : rc);
            if (mask_at(dtm, b * L2_ + L_ + rc, mode)) {
                const float* trow = tag + (size_t)(b * L_ + rc) * D_;
                float a = 0.f;
                #pragma unroll
                for (int i = 0; i < 16; i++) a += brow[lane + 32 * i] * trow[lane + 32 * i];
                #pragma unroll
                for (int o = 16; o; o >>= 1) a += __shfl_xor_sync(0xffffffffu, a, o);
                ts += logden - a * INV_TEMP;
                tc += 1.f;
            }
        }
    }
    __shared__ float sS[8], sC[8];
    if (lane == 0) { sS[warp] = ts; sC[warp] = tc; }
    __syncthreads();
    if (threadIdx.x == 0) {
        float s = 0.f, c = 0.f;
        #pragma unroll
        for (int i = 0; i < 8; i++) { s += sS[i]; c += sC[i]; }
        g_ptr_S[blockIdx.x] = s; g_ptr_C[blockIdx.x] = c;
    }
}

// ======================= span contrastive (warp-per-row, barrier-free, hw exp) =======================
__global__ void __launch_bounds__(256) k_contr(const float* __restrict__ rsim,
                                               const float* __restrict__ csim,
                                               const float* __restrict__ rco,
                                               const float* __restrict__ cco) {
    int warp = threadIdx.x >> 5, lane = threadIdx.x & 31;
    int row = blockIdx.x * 8 + warp;         // 0..16383
    int slot = row >> 13;
    int bi = row & 8191;
    int i = bi & 1023;                       // diagonal index
    const float* sim  = slot ? csim : rsim;
    const float* coef = slot ? cco : rco;
    const float4* s4 = (const float4*)(sim  + (size_t)bi * L_);
    const float4* c4 = (const float4*)(coef + (size_t)bi * L_);

    float s[32];
    float W = 0.f, WSr = 0.f, m = -1e30f;
    #pragma unroll
    for (int j = 0; j < 8; j++) {
        float4 sv = s4[lane + 32 * j];
        float4 cv = c4[lane + 32 * j];
        float a0 = sv.x * INV_TEMP, a1 = sv.y * INV_TEMP;
        float a2 = sv.z * INV_TEMP, a3 = sv.w * INV_TEMP;
        s[4 * j] = a0; s[4 * j + 1] = a1; s[4 * j + 2] = a2; s[4 * j + 3] = a3;
        m = fmaxf(m, fmaxf(fmaxf(a0, a1), fmaxf(a2, a3)));
        float w0 = fmaxf(cv.x, 0.f), w1 = fmaxf(cv.y, 0.f);
        float w2 = fmaxf(cv.z, 0.f), w3 = fmaxf(cv.w, 0.f);
        W += (w0 + w1) + (w2 + w3);
        WSr += w0 * a0 + w1 * a1 + w2 * a2 + w3 * a3;
    }
    #pragma unroll
    for (int o = 16; o; o >>= 1) m = fmaxf(m, __shfl_xor_sync(0xffffffffu, m, o));

    float es = 0.f, ed = 0.f;
    #pragma unroll
    for (int j = 0; j < 8; j++) {
        #pragma unroll
        for (int q = 0; q < 4; q++) {
            float e = __expf(s[4 * j + q] - m);   // arg <= 0 (max-subtracted)
            es += e;
            if (4 * lane + 128 * j + q == i) ed = e;
        }
    }
    #pragma unroll
    for (int o = 16; o; o >>= 1) {
        es  += __shfl_xor_sync(0xffffffffu, es, o);
        W   += __shfl_xor_sync(0xffffffffu, W, o);
        WSr += __shfl_xor_sync(0xffffffffu, WSr, o);
        ed  += __shfl_xor_sync(0xffffffffu, ed, o);
    }
    if (lane == 0) {
        float den = es - ed;
        float logden = logf(den + EPSF);
        float haspos = W > 0.f ? 1.f : 0.f;
        float WS = WSr - m * W;              // sum(w * (s - m))
        float loss = (logden * W - WS) / (W + EPSF);
        g_con_L[slot * (B_ * L_) + bi] = haspos * loss;
        g_con_P[slot * (B_ * L_) + bi] = haspos;
    }
}

// ======================= final deterministic combine =======================
__device__ float blk_sum(const float* p, int n, volatile float* sh) {
    float a = 0.f;
    for (int i = threadIdx.x; i < n; i += 256) a += p[i];
    #pragma unroll
    for (int o = 16; o; o >>= 1) a += __shfl_xor_sync(0xffffffffu, a, o);
    __syncthreads();
    if ((threadIdx.x & 31) == 0) sh[threadIdx.x >> 5] = a;
    __syncthreads();
    if (threadIdx.x == 0) {
        float r = 0.f;
        for (int w = 0; w < 8; w++) r += sh[w];
        sh[8] = r;
    }
    __syncthreads();
    float r = sh[8];
    __syncthreads();
    return r;
}

__global__ void __launch_bounds__(256) k_final(float* __restrict__ out) {
    __shared__ float sh[16];
    float clsS = blk_sum(g_cls_S, 1024, sh);
    float clsC = blk_sum(g_cls_C, 1024, sh);
    float cls = clsS / fmaxf(clsC, 1.f);

    float emp = 0.f;
    for (int b = 0; b < B_; b++) {
        float S = blk_sum(g_emp_S + b * 128, 128, sh);
        float C = blk_sum(g_emp_C + b * 128, 128, sh);
        emp += S / fmaxf(C, 1.f);
    }
    emp *= (1.f / B_);

    float ptrS = blk_sum(g_ptr_S, 1024, sh);
    float ptrC = blk_sum(g_ptr_C, 1024, sh);
    float ptr = (ptrC > 0.f) ? ptrS / fmaxf(ptrC, 1.f) : 0.f;

    float rL = blk_sum(g_con_L, B_ * L_, sh);
    float rP = blk_sum(g_con_P, B_ * L_, sh);
    float row = (rP > 0.f) ? rL / fmaxf(rP, 1.f) : 0.f;

    float cL = blk_sum(g_con_L + B_ * L_, B_ * L_, sh);
    float cP = blk_sum(g_con_P + B_ * L_, B_ * L_, sh);
    float col = (cP > 0.f) ? cL / fmaxf(cP, 1.f) : 0.f;

    if (threadIdx.x == 0) {
        out[1] = cls; out[2] = ptr; out[3] = emp; out[4] = row; out[5] = col;
        out[0] = cls + ptr + emp + 0.5f * row + 0.5f * col;
    }
}

// ======================= launch =======================
extern "C" void kernel_launch(void* const* d_in, const int* in_sizes, int n_in,
                              void* d_out, int out_size) {
    (void)in_sizes; (void)n_in; (void)out_size;
    const int*           tok  = (const int*)d_in[0];            // token_ids (B,L)
    const int*           bidx = (const int*)d_in[1];            // box_indices (B,L,K)
    const void*          dtm  = d_in[2];                        // data_tag_mask (B,2L)
    const void*          att  = d_in[3];                        // attention_mask (B,2L)
    const float*         tlog = (const float*)d_in[4];          // tag_logits (B,L,V)
    const float*         boxp = (const float*)d_in[5];          // box_proj (B,L,D)
    const float*         tagp = (const float*)d_in[6];          // tag_proj (B,L,D)
    const float*         empp = (const float*)d_in[7];          // empty_proj (B,1,D)
    const float*         rsim = (const float*)d_in[8];
    const float*         csim = (const float*)d_in[9];
    const float*         rco  = (const float*)d_in[10];
    const float*         cco  = (const float*)d_in[11];
    float* out = (float*)d_out;

    static int inited = 0;
    static cudaStream_t s_side;
    static cudaEvent_t ev_fork, ev_join;
    if (!inited) {
        cudaFuncSetAttribute(k_gemm, cudaFuncAttributeMaxDynamicSharedMemorySize, GEMM_DYN_SMEM);
        cudaStreamCreateWithFlags(&s_side, cudaStreamNonBlocking);
        cudaEventCreateWithFlags(&ev_fork, cudaEventDisableTiming);
        cudaEventCreateWithFlags(&ev_join, cudaEventDisableTiming);
        inited = 1;
    }

    // fork: independent kernels (cls, contrastive) on the side stream
    cudaEventRecord(ev_fork, 0);
    cudaStreamWaitEvent(s_side, ev_fork, 0);
    k_cls<<<1024, 256, 0, s_side>>>(tlog, tok);
    k_contr<<<2048, 256, 0, s_side>>>(rsim, csim, rco, cco);
    cudaEventRecord(ev_join, s_side);

    // main chain: cvt(+empty BCE) -> gemm -> ptr
    k_cvt<<<2048, 256>>>(boxp, tagp, empp, att, dtm);
    dim3 gg(8, 8, B_);
    k_gemm<<<gg, 256, GEMM_DYN_SMEM>>>(att, dtm);
    k_ptr<<<1024, 256>>>(boxp, tagp, bidx, att, dtm);

    // join, then final combine
    cudaStreamWaitEvent(0, ev_join, 0);
    k_final<<<1, 256>>>(out);
}

// round 15
// speedup vs baseline: 1.0838x; 1.0838x over previous
#include <cuda_runtime.h>
#include <cuda_pipeline.h>
#include <cuda_bf16.h>
#include <math.h>
#include <stdint.h>
#include <mma.h>

using namespace nvcuda;

// Problem constants (fixed by the reference)
#define B_  8
#define L_  1024
#define D_  512
#define V_  64
#define K_  8
#define L2_ 2048            // masks are (B, 2L)
#define INV_TEMP 10.0f
#define EPSF 1e-10f
#define KCH 64              // k-chunk per pipeline stage (4 x k16 mma steps)
#define KPAD 72             // padded row stride in halfs (144 B)
#define NSTAGE 2
#define STAGE_ELEMS (2 * 128 * KPAD)              // bf16 elems per stage (A+B)
#define GEMM_DYN_SMEM (NSTAGE * STAGE_ELEMS * 2)  // 73728 bytes

// -------- deterministic scratch (device globals; no allocations) --------
__device__ __nv_bfloat16 g_boxH[B_ * L_ * D_];   // bf16 box_proj (8 MB)
__device__ __nv_bfloat16 g_tagH[B_ * L_ * D_];   // bf16 tag_proj (8 MB)
__device__ float g_den_part[B_ * L_ * 8];    // [b*L+l][t_tile(128-wide)] masked exp partial sums
__device__ float g_cls_S[1024];
__device__ float g_cls_C[1024];
__device__ float g_emp_S[1024];              // [b*128 + chunk]
__device__ float g_emp_C[1024];
__device__ float g_ptr_S[1024];
__device__ float g_ptr_C[1024];
__device__ float g_con_L[2048];              // per-block partials (blocks 0-1023: row, 1024-2047: col)
__device__ float g_con_P[2048];

// ---- inline mask-mode probe: attention_mask[:, :L] is guaranteed all-True ----
// word 0 of att: 1 -> int32 masks, 0x3F800000 -> float32, else packed bytes.
__device__ __forceinline__ int mask_mode_of(const void* att) {
    unsigned int w = *(const unsigned int*)att;
    if (w == 1u) return 1;
    if (w == 0x3F800000u) return 2;
    return 0;
}

__device__ __forceinline__ int mask_at(const void* p, int idx, int mode) {
    if (mode == 1) return ((const int*)p)[idx] != 0;
    if (mode == 2) return ((const float*)p)[idx] != 0.0f;
    return ((const unsigned char*)p)[idx] != 0;
}

// ======================= fp32 -> bf16 convert pass (+ fused empty-BCE) =======================
__global__ void __launch_bounds__(256) k_cvt(const float* __restrict__ boxp,
                                             const float* __restrict__ tagp,
                                             const float* __restrict__ emp,
                                             const void* __restrict__ att,
                                             const void* __restrict__ dtm) {
    int blk = blockIdx.x;
    if (blk < 1024) {
        size_t base = ((size_t)blk * 256 + threadIdx.x) * 16;
        const float4* s = (const float4*)(boxp + base);
        __nv_bfloat162* d = (__nv_bfloat162*)(g_boxH + base);
        float4 v0 = s[0], v1 = s[1], v2 = s[2], v3 = s[3];   // batch loads (MLP 4)
        d[0] = __floats2bfloat162_rn(v0.x, v0.y); d[1] = __floats2bfloat162_rn(v0.z, v0.w);
        d[2] = __floats2bfloat162_rn(v1.x, v1.y); d[3] = __floats2bfloat162_rn(v1.z, v1.w);
        d[4] = __floats2bfloat162_rn(v2.x, v2.y); d[5] = __floats2bfloat162_rn(v2.z, v2.w);
        d[6] = __floats2bfloat162_rn(v3.x, v3.y); d[7] = __floats2bfloat162_rn(v3.z, v3.w);
        return;
    }
    // tag half: 8 warps, warp per row (8 rows per block)
    int mode = mask_mode_of(att);
    int bt = blk - 1024;                     // 0..1023
    int warp = threadIdx.x >> 5, lane = threadIdx.x & 31;
    int row = bt * 8 + warp;                 // = b*L + t
    int b = row >> 10, t = row & 1023;
    const float4* tp4 = (const float4*)(tagp + (size_t)row * D_);
    const float4* ep4 = (const float4*)(emp + (size_t)b * D_);
    __nv_bfloat162* dp = (__nv_bfloat162*)(g_tagH + (size_t)row * D_);
    float acc = 0.f;
    #pragma unroll
    for (int i = 0; i < 4; i++) {
        int idx = lane + 32 * i;             // float4 index within row
        float4 v = tp4[idx];
        float4 e = ep4[idx];
        acc += v.x * e.x + v.y * e.y + v.z * e.z + v.w * e.w;
        dp[2 * idx]     = __floats2bfloat162_rn(v.x, v.y);
        dp[2 * idx + 1] = __floats2bfloat162_rn(v.z, v.w);
    }
    #pragma unroll
    for (int o = 16; o; o >>= 1) acc += __shfl_xor_sync(0xffffffffu, acc, o);
    int a = mask_at(att, b * L2_ + L_ + t, mode);
    int d = mask_at(dtm, b * L2_ + L_ + t, mode);
    float tgt = (a && !d) ? 1.f : 0.f;
    float el = acc;
    float bce = fmaxf(el, 0.f) + log1pf(__expf(-fabsf(el))) - el * tgt;
    __shared__ float sS[8], sC[8];
    if (lane == 0) { sS[warp] = a ? bce : 0.f; sC[warp] = (float)a; }
    __syncthreads();
    if (threadIdx.x == 0) {
        float s = 0.f, c = 0.f;
        #pragma unroll
        for (int i = 0; i < 8; i++) { s += sS[i]; c += sC[i]; }
        g_emp_S[bt] = s; g_emp_C[bt] = c;
    }
}

// ======================= cls loss =======================
__global__ void __launch_bounds__(256) k_cls(const float* __restrict__ logits,
                                             const int* __restrict__ tok) {
    int warp = threadIdx.x >> 5, lane = threadIdx.x & 31;
    int row = blockIdx.x * 8 + warp;
    const float* p = logits + (size_t)row * V_;
    float s0 = p[lane], s1 = p[lane + 32];
    float m = fmaxf(s0, s1);
    #pragma unroll
    for (int o = 16; o; o >>= 1) m = fmaxf(m, __shfl_xor_sync(0xffffffffu, m, o));
    float e = __expf(s0 - m) + __expf(s1 - m);
    float ss = s0 + s1;
    int t = tok[row];
    float st = (lane == t ? s0 : 0.f) + (lane + 32 == t ? s1 : 0.f);
    #pragma unroll
    for (int o = 16; o; o >>= 1) {
        e  += __shfl_xor_sync(0xffffffffu, e, o);
        ss += __shfl_xor_sync(0xffffffffu, ss, o);
        st += __shfl_xor_sync(0xffffffffu, st, o);
    }
    float lse = m + logf(e);
    float per = 0.9f * (lse - st) + 0.1f * (lse - ss * (1.0f / V_));
    float valid = (t > 3) ? 1.f : 0.f;   // SPECIAL_IDS = 0..3
    __shared__ float sS[8], sC[8];
    if (lane == 0) { sS[warp] = per * valid; sC[warp] = valid; }
    __syncthreads();
    if (threadIdx.x == 0) {
        float a = 0.f, c = 0.f;
        #pragma unroll
        for (int i = 0; i < 8; i++) { a += sS[i]; c += sC[i]; }
        g_cls_S[blockIdx.x] = a; g_cls_C[blockIdx.x] = c;
    }
}

// ======================= wmma bf16 GEMM + masked exp-sum (2-stage, KCH=64) =======================
__global__ void __launch_bounds__(256, 2) k_gemm(const void* __restrict__ att,
                                                 const void* __restrict__ dtm) {
    extern __shared__ __nv_bfloat16 dyn[];   // NSTAGE stages of [A|B][128][KPAD]
    __shared__ float red[128][2];
    __shared__ unsigned char sdtm[128];

    int mode = mask_mode_of(att);
    int b = blockIdx.z, lt = blockIdx.y, tt = blockIdx.x;
    int tid = threadIdx.x;
    int wid = tid >> 5, lane = tid & 31;
    int wm = wid >> 1, wn = wid & 1;     // 4 x 2 warp grid

    if (tid < 128) sdtm[tid] = (unsigned char)mask_at(dtm, b * L2_ + L_ + tt * 128 + tid, mode);

    const __nv_bfloat16* A  = g_boxH + (size_t)(b * L_ + lt * 128) * D_;
    const __nv_bfloat16* Bt = g_tagH + (size_t)(b * L_ + tt * 128) * D_;

    wmma::fragment<wmma::accumulator, 16, 16, 16, float> acc[2][4];
    #pragma unroll
    for (int mi = 0; mi < 2; mi++)
        #pragma unroll
        for (int ni = 0; ni < 4; ni++)
            wmma::fill_fragment(acc[mi][ni], 0.0f);

    auto prefetch = [&](int s, int kc) {
        __nv_bfloat16* stA = dyn + s * STAGE_ELEMS;
        __nv_bfloat16* stB = stA + 128 * KPAD;
        #pragma unroll
        for (int it = 0; it < 4; it++) {
            int a = tid + it * 256;              // 0..1023
            int r = a >> 3, c8 = (a & 7) * 8;    // 8 chunks of 8 halfs per row
            __pipeline_memcpy_async(&stA[r * KPAD + c8], A + (size_t)r * D_ + kc + c8, 16);
        }
        #pragma unroll
        for (int it = 0; it < 4; it++) {
            int a = tid + it * 256;
            int r = a >> 3, c8 = (a & 7) * 8;
            __pipeline_memcpy_async(&stB[r * KPAD + c8], Bt + (size_t)r * D_ + kc + c8, 16);
        }
        __pipeline_commit();
    };

    const int NIT = D_ / KCH;            // 8
    prefetch(0, 0);
    for (int i = 0; i < NIT; i++) {
        if (i + 1 < NIT) prefetch((i + 1) & 1, (i + 1) * KCH);
        __pipeline_wait_prior((i + 1 < NIT) ? 1 : 0);
        __syncthreads();
        __nv_bfloat16* stA = dyn + (i & 1) * STAGE_ELEMS;
        __nv_bfloat16* stB = stA + 128 * KPAD;
        #pragma unroll
        for (int kk = 0; kk < KCH; kk += 16) {
            wmma::fragment<wmma::matrix_a, 16, 16, 16, __nv_bfloat16, wmma::row_major> af[2];
            #pragma unroll
            for (int mi = 0; mi < 2; mi++)
                wmma::load_matrix_sync(af[mi], &stA[(wm * 32 + mi * 16) * KPAD + kk], KPAD);
            wmma::fragment<wmma::matrix_b, 16, 16, 16, __nv_bfloat16, wmma::col_major> bf[4];
            #pragma unroll
            for (int ni = 0; ni < 4; ni++)
                wmma::load_matrix_sync(bf[ni], &stB[(wn * 64 + ni * 16) * KPAD + kk], KPAD);
            #pragma unroll
            for (int mi = 0; mi < 2; mi++)
                #pragma unroll
                for (int ni = 0; ni < 4; ni++)
                    wmma::mma_sync(acc[mi][ni], af[mi], bf[ni], acc[mi][ni]);
        }
        __syncthreads();
    }

    // epilogue: masked exp + row reduce; per-warp fp32 scratch aliased onto dyn
    float* scr = (float*)dyn + wid * (16 * 20);   // 1280B/warp slice
    int r = lane & 15, h = lane >> 4;    // row within frag, column half
    #pragma unroll
    for (int mi = 0; mi < 2; mi++) {
        float rowsum = 0.f;
        #pragma unroll
        for (int ni = 0; ni < 4; ni++) {
            wmma::store_matrix_sync(scr, acc[mi][ni], 20, wmma::mem_row_major);
            __syncwarp();
            float s = 0.f;
            #pragma unroll
            for (int c = 0; c < 8; c++) {
                int col = h * 8 + c;
                int gc = wn * 64 + ni * 16 + col;
                if (sdtm[gc]) s += __expf(scr[r * 20 + col] * INV_TEMP);
            }
            rowsum += s;
            __syncwarp();
        }
        rowsum += __shfl_xor_sync(0xffffffffu, rowsum, 16);
        if (h == 0) red[wm * 32 + mi * 16 + r][wn] = rowsum;
    }
    __syncthreads();
    if (tid < 128) {
        float s = red[tid][0] + red[tid][1];
        g_den_part[(size_t)(b * L_ + lt * 128 + tid) * 8 + tt] = s;
    }
}

// ======================= pointer loss (targets + combine) =======================
__global__ void __launch_bounds__(256) k_ptr(const float* __restrict__ box,
                                             const float* __restrict__ tag,
                                             const int* __restrict__ bidx,
                                             const void* __restrict__ att,
                                             const void* __restrict__ dtm) {
    int mode = mask_mode_of(att);
    int warp = threadIdx.x >> 5, lane = threadIdx.x & 31;
    int gw = blockIdx.x * 8 + warp;          // gw = b*L + l
    int b = gw >> 10;
    float dv = (lane < 8) ? g_den_part[(size_t)gw * 8 + lane] : 0.f;
    #pragma unroll
    for (int o = 16; o; o >>= 1) dv += __shfl_xor_sync(0xffffffffu, dv, o);
    float logden = logf(dv + EPSF);
    const int* bi = bidx + (size_t)gw * K_;
    const float* brow = box + (size_t)gw * D_;
    float ts = 0.f, tc = 0.f;
    bool valid = true;
    for (int k = 0; k < K_; k++) {
        int idx = bi[k];
        if (idx < 0) valid = false;
        if (valid) {
            int rc = idx - L_;
            rc = rc < 0 ? 0 : (rc > L_ - 1 ? L_ - 1 : rc);
            if (mask_at(dtm, b * L2_ + L_ + rc, mode)) {
                const float* trow = tag + (size_t)(b * L_ + rc) * D_;
                float a = 0.f;
                #pragma unroll
                for (int i = 0; i < 16; i++) a += brow[lane + 32 * i] * trow[lane + 32 * i];
                #pragma unroll
                for (int o = 16; o; o >>= 1) a += __shfl_xor_sync(0xffffffffu, a, o);
                ts += logden - a * INV_TEMP;
                tc += 1.f;
            }
        }
    }
    __shared__ float sS[8], sC[8];
    if (lane == 0) { sS[warp] = ts; sC[warp] = tc; }
    __syncthreads();
    if (threadIdx.x == 0) {
        float s = 0.f, c = 0.f;
        #pragma unroll
        for (int i = 0; i < 8; i++) { s += sS[i]; c += sC[i]; }
        g_ptr_S[blockIdx.x] = s; g_ptr_C[blockIdx.x] = c;
    }
}

// ======================= span contrastive (warp-per-row, block-reduced output) =======================
// 2048 blocks x 8 warps = 16384 rows. Blocks 0-1023: row-slot, 1024-2047: col-slot
// (exact: 8192 rows / 8 warps = 1024 blocks per slot). Each block writes ONE
// (loss, haspos) partial pair -> k_final reads 8x less.
__global__ void __launch_bounds__(256) k_contr(const float* __restrict__ rsim,
                                               const float* __restrict__ csim,
                                               const float* __restrict__ rco,
                                               const float* __restrict__ cco) {
    int warp = threadIdx.x >> 5, lane = threadIdx.x & 31;
    int row = blockIdx.x * 8 + warp;         // 0..16383
    int slot = row >> 13;
    int bi = row & 8191;
    int i = bi & 1023;                       // diagonal index
    const float* sim  = slot ? csim : rsim;
    const float* coef = slot ? cco : rco;
    const float4* s4 = (const float4*)(sim  + (size_t)bi * L_);
    const float4* c4 = (const float4*)(coef + (size_t)bi * L_);

    float s[32];
    float W = 0.f, WSr = 0.f, m = -1e30f;
    #pragma unroll
    for (int j = 0; j < 8; j++) {
        float4 sv = s4[lane + 32 * j];
        float4 cv = c4[lane + 32 * j];
        float a0 = sv.x * INV_TEMP, a1 = sv.y * INV_TEMP;
        float a2 = sv.z * INV_TEMP, a3 = sv.w * INV_TEMP;
        s[4 * j] = a0; s[4 * j + 1] = a1; s[4 * j + 2] = a2; s[4 * j + 3] = a3;
        m = fmaxf(m, fmaxf(fmaxf(a0, a1), fmaxf(a2, a3)));
        float w0 = fmaxf(cv.x, 0.f), w1 = fmaxf(cv.y, 0.f);
        float w2 = fmaxf(cv.z, 0.f), w3 = fmaxf(cv.w, 0.f);
        W += (w0 + w1) + (w2 + w3);
        WSr += w0 * a0 + w1 * a1 + w2 * a2 + w3 * a3;
    }
    #pragma unroll
    for (int o = 16; o; o >>= 1) m = fmaxf(m, __shfl_xor_sync(0xffffffffu, m, o));

    float es = 0.f, ed = 0.f;
    #pragma unroll
    for (int j = 0; j < 8; j++) {
        #pragma unroll
        for (int q = 0; q < 4; q++) {
            float e = __expf(s[4 * j + q] - m);   // arg <= 0 (max-subtracted)
            es += e;
            if (4 * lane + 128 * j + q == i) ed = e;
        }
    }
    #pragma unroll
    for (int o = 16; o; o >>= 1) {
        es  += __shfl_xor_sync(0xffffffffu, es, o);
        W   += __shfl_xor_sync(0xffffffffu, W, o);
        WSr += __shfl_xor_sync(0xffffffffu, WSr, o);
        ed  += __shfl_xor_sync(0xffffffffu, ed, o);
    }
    __shared__ float sL[8], sP[8];
    if (lane == 0) {
        float den = es - ed;
        float logden = logf(den + EPSF);
        float haspos = W > 0.f ? 1.f : 0.f;
        float WS = WSr - m * W;              // sum(w * (s - m))
        float loss = (logden * W - WS) / (W + EPSF);
        sL[warp] = haspos * loss;
        sP[warp] = haspos;
    }
    __syncthreads();
    if (threadIdx.x == 0) {
        float l = 0.f, p = 0.f;
        #pragma unroll
        for (int w = 0; w < 8; w++) { l += sL[w]; p += sP[w]; }
        g_con_L[blockIdx.x] = l;
        g_con_P[blockIdx.x] = p;
    }
}

// ======================= final deterministic combine =======================
// MLP-4 strided sum: 4 independent accumulators keep 4 loads in flight.
__device__ float blk_sum(const float* p, int n, volatile float* sh) {
    float a0 = 0.f, a1 = 0.f, a2 = 0.f, a3 = 0.f;
    int i = threadIdx.x;
    for (; i < n - 768; i += 1024) {
        a0 += p[i]; a1 += p[i + 256]; a2 += p[i + 512]; a3 += p[i + 768];
    }
    for (; i < n; i += 256) a0 += p[i];
    float a = (a0 + a1) + (a2 + a3);
    #pragma unroll
    for (int o = 16; o; o >>= 1) a += __shfl_xor_sync(0xffffffffu, a, o);
    __syncthreads();
    if ((threadIdx.x & 31) == 0) sh[threadIdx.x >> 5] = a;
    __syncthreads();
    if (threadIdx.x == 0) {
        float r = 0.f;
        for (int w = 0; w < 8; w++) r += sh[w];
        sh[8] = r;
    }
    __syncthreads();
    float r = sh[8];
    __syncthreads();
    return r;
}

__global__ void __launch_bounds__(256) k_final(float* __restrict__ out) {
    __shared__ float sh[16];
    float clsS = blk_sum(g_cls_S, 1024, sh);
    float clsC = blk_sum(g_cls_C, 1024, sh);
    float cls = clsS / fmaxf(clsC, 1.f);

    float emp = 0.f;
    for (int b = 0; b < B_; b++) {
        float S = blk_sum(g_emp_S + b * 128, 128, sh);
        float C = blk_sum(g_emp_C + b * 128, 128, sh);
        emp += S / fmaxf(C, 1.f);
    }
    emp *= (1.f / B_);

    float ptrS = blk_sum(g_ptr_S, 1024, sh);
    float ptrC = blk_sum(g_ptr_C, 1024, sh);
    float ptr = (ptrC > 0.f) ? ptrS / fmaxf(ptrC, 1.f) : 0.f;

    float rL = blk_sum(g_con_L, 1024, sh);
    float rP = blk_sum(g_con_P, 1024, sh);
    float row = (rP > 0.f) ? rL / fmaxf(rP, 1.f) : 0.f;

    float cL = blk_sum(g_con_L + 1024, 1024, sh);
    float cP = blk_sum(g_con_P + 1024, 1024, sh);
    float col = (cP > 0.f) ? cL / fmaxf(cP, 1.f) : 0.f;

    if (threadIdx.x == 0) {
        out[1] = cls; out[2] = ptr; out[3] = emp; out[4] = row; out[5] = col;
        out[0] = cls + ptr + emp + 0.5f * row + 0.5f * col;
    }
}

// ======================= launch =======================
extern "C" void kernel_launch(void* const* d_in, const int* in_sizes, int n_in,
                              void* d_out, int out_size) {
    (void)in_sizes; (void)n_in; (void)out_size;
    const int*           tok  = (const int*)d_in[0];            // token_ids (B,L)
    const int*           bidx = (const int*)d_in[1];            // box_indices (B,L,K)
    const void*          dtm  = d_in[2];                        // data_tag_mask (B,2L)
    const void*          att  = d_in[3];                        // attention_mask (B,2L)
    const float*         tlog = (const float*)d_in[4];          // tag_logits (B,L,V)
    const float*         boxp = (const float*)d_in[5];          // box_proj (B,L,D)
    const float*         tagp = (const float*)d_in[6];          // tag_proj (B,L,D)
    const float*         empp = (const float*)d_in[7];          // empty_proj (B,1,D)
    const float*         rsim = (const float*)d_in[8];
    const float*         csim = (const float*)d_in[9];
    const float*         rco  = (const float*)d_in[10];
    const float*         cco  = (const float*)d_in[11];
    float* out = (float*)d_out;

    static int inited = 0;
    static cudaStream_t s_side;
    static cudaEvent_t ev_fork, ev_join;
    if (!inited) {
        cudaFuncSetAttribute(k_gemm, cudaFuncAttributeMaxDynamicSharedMemorySize, GEMM_DYN_SMEM);
        cudaStreamCreateWithFlags(&s_side, cudaStreamNonBlocking);
        cudaEventCreateWithFlags(&ev_fork, cudaEventDisableTiming);
        cudaEventCreateWithFlags(&ev_join, cudaEventDisableTiming);
        inited = 1;
    }

    // fork: independent kernels (cls, contrastive) on the side stream
    cudaEventRecord(ev_fork, 0);
    cudaStreamWaitEvent(s_side, ev_fork, 0);
    k_cls<<<1024, 256, 0, s_side>>>(tlog, tok);
    k_contr<<<2048, 256, 0, s_side>>>(rsim, csim, rco, cco);
    cudaEventRecord(ev_join, s_side);

    // main chain: cvt(+empty BCE) -> gemm -> ptr
    k_cvt<<<2048, 256>>>(boxp, tagp, empp, att, dtm);
    dim3 gg(8, 8, B_);
    k_gemm<<<gg, 256, GEMM_DYN_SMEM>>>(att, dtm);
    k_ptr<<<1024, 256>>>(boxp, tagp, bidx, att, dtm);

    // join, then final combine
    cudaStreamWaitEvent(0, ev_join, 0);
    k_final<<<1, 256>>>(out);
}

// round 16
// speedup vs baseline: 1.0846x; 1.0007x over previous
#include <cuda_runtime.h>
#include <cuda_pipeline.h>
#include <cuda_bf16.h>
#include <math.h>
#include <stdint.h>
#include <mma.h>

using namespace nvcuda;

// Problem constants (fixed by the reference)
#define B_  8
#define L_  1024
#define D_  512
#define V_  64
#define K_  8
#define L2_ 2048            // masks are (B, 2L)
#define INV_TEMP 10.0f
#define EPSF 1e-10f
#define KCH 64              // k-chunk per pipeline stage (4 x k16 mma steps)
#define KPAD 72             // padded row stride in halfs (144 B)
#define NSTAGE 3
#define STAGE_ELEMS (2 * 128 * KPAD)              // bf16 elems per stage (A+B)
#define GEMM_DYN_SMEM (NSTAGE * STAGE_ELEMS * 2)  // 110592 bytes

// -------- deterministic scratch (device globals; no allocations) --------
__device__ __nv_bfloat16 g_boxH[B_ * L_ * D_];   // bf16 box_proj (8 MB)
__device__ __nv_bfloat16 g_tagH[B_ * L_ * D_];   // bf16 tag_proj (8 MB)
__device__ float g_den_part[B_ * L_ * 8];    // [b*L+l][t_tile(128-wide)] masked exp partial sums
__device__ float g_cls_S[1024];
__device__ float g_cls_C[1024];
__device__ float g_emp_S[1024];              // [b*128 + chunk]
__device__ float g_emp_C[1024];
__device__ float g_ptr_S[1024];
__device__ float g_ptr_C[1024];
__device__ float g_con_L[2048];              // per-block partials (blocks 0-1023: row, 1024-2047: col)
__device__ float g_con_P[2048];

// ---- inline mask-mode probe: attention_mask[:, :L] is guaranteed all-True ----
// word 0 of att: 1 -> int32 masks, 0x3F800000 -> float32, else packed bytes.
__device__ __forceinline__ int mask_mode_of(const void* att) {
    unsigned int w = *(const unsigned int*)att;
    if (w == 1u) return 1;
    if (w == 0x3F800000u) return 2;
    return 0;
}

__device__ __forceinline__ int mask_at(const void* p, int idx, int mode) {
    if (mode == 1) return ((const int*)p)[idx] != 0;
    if (mode == 2) return ((const float*)p)[idx] != 0.0f;
    return ((const unsigned char*)p)[idx] != 0;
}

// ======================= fp32 -> bf16 convert pass (+ fused empty-BCE) =======================
__global__ void __launch_bounds__(256) k_cvt(const float* __restrict__ boxp,
                                             const float* __restrict__ tagp,
                                             const float* __restrict__ emp,
                                             const void* __restrict__ att,
                                             const void* __restrict__ dtm) {
    int blk = blockIdx.x;
    if (blk < 1024) {
        size_t base = ((size_t)blk * 256 + threadIdx.x) * 16;
        const float4* s = (const float4*)(boxp + base);
        __nv_bfloat162* d = (__nv_bfloat162*)(g_boxH + base);
        float4 v0 = s[0], v1 = s[1], v2 = s[2], v3 = s[3];   // batch loads (MLP 4)
        d[0] = __floats2bfloat162_rn(v0.x, v0.y); d[1] = __floats2bfloat162_rn(v0.z, v0.w);
        d[2] = __floats2bfloat162_rn(v1.x, v1.y); d[3] = __floats2bfloat162_rn(v1.z, v1.w);
        d[4] = __floats2bfloat162_rn(v2.x, v2.y); d[5] = __floats2bfloat162_rn(v2.z, v2.w);
        d[6] = __floats2bfloat162_rn(v3.x, v3.y); d[7] = __floats2bfloat162_rn(v3.z, v3.w);
        return;
    }
    // tag half: 8 warps, warp per row (8 rows per block)
    int mode = mask_mode_of(att);
    int bt = blk - 1024;                     // 0..1023
    int warp = threadIdx.x >> 5, lane = threadIdx.x & 31;
    int row = bt * 8 + warp;                 // = b*L + t
    int b = row >> 10, t = row & 1023;
    const float4* tp4 = (const float4*)(tagp + (size_t)row * D_);
    const float4* ep4 = (const float4*)(emp + (size_t)b * D_);
    __nv_bfloat162* dp = (__nv_bfloat162*)(g_tagH + (size_t)row * D_);
    float acc = 0.f;
    #pragma unroll
    for (int i = 0; i < 4; i++) {
        int idx = lane + 32 * i;             // float4 index within row
        float4 v = tp4[idx];
        float4 e = ep4[idx];
        acc += v.x * e.x + v.y * e.y + v.z * e.z + v.w * e.w;
        dp[2 * idx]     = __floats2bfloat162_rn(v.x, v.y);
        dp[2 * idx + 1] = __floats2bfloat162_rn(v.z, v.w);
    }
    #pragma unroll
    for (int o = 16; o; o >>= 1) acc += __shfl_xor_sync(0xffffffffu, acc, o);
    int a = mask_at(att, b * L2_ + L_ + t, mode);
    int d = mask_at(dtm, b * L2_ + L_ + t, mode);
    float tgt = (a && !d) ? 1.f : 0.f;
    float el = acc;
    float bce = fmaxf(el, 0.f) + log1pf(__expf(-fabsf(el))) - el * tgt;
    __shared__ float sS[8], sC[8];
    if (lane == 0) { sS[warp] = a ? bce : 0.f; sC[warp] = (float)a; }
    __syncthreads();
    if (threadIdx.x == 0) {
        float s = 0.f, c = 0.f;
        #pragma unroll
        for (int i = 0; i < 8; i++) { s += sS[i]; c += sC[i]; }
        g_emp_S[bt] = s; g_emp_C[bt] = c;
    }
}

// ======================= cls loss =======================
__global__ void __launch_bounds__(256) k_cls(const float* __restrict__ logits,
                                             const int* __restrict__ tok) {
    int warp = threadIdx.x >> 5, lane = threadIdx.x & 31;
    int row = blockIdx.x * 8 + warp;
    const float* p = logits + (size_t)row * V_;
    float s0 = p[lane], s1 = p[lane + 32];
    float m = fmaxf(s0, s1);
    #pragma unroll
    for (int o = 16; o; o >>= 1) m = fmaxf(m, __shfl_xor_sync(0xffffffffu, m, o));
    float e = __expf(s0 - m) + __expf(s1 - m);
    float ss = s0 + s1;
    int t = tok[row];
    float st = (lane == t ? s0 : 0.f) + (lane + 32 == t ? s1 : 0.f);
    #pragma unroll
    for (int o = 16; o; o >>= 1) {
        e  += __shfl_xor_sync(0xffffffffu, e, o);
        ss += __shfl_xor_sync(0xffffffffu, ss, o);
        st += __shfl_xor_sync(0xffffffffu, st, o);
    }
    float lse = m + logf(e);
    float per = 0.9f * (lse - st) + 0.1f * (lse - ss * (1.0f / V_));
    float valid = (t > 3) ? 1.f : 0.f;   // SPECIAL_IDS = 0..3
    __shared__ float sS[8], sC[8];
    if (lane == 0) { sS[warp] = per * valid; sC[warp] = valid; }
    __syncthreads();
    if (threadIdx.x == 0) {
        float a = 0.f, c = 0.f;
        #pragma unroll
        for (int i = 0; i < 8; i++) { a += sS[i]; c += sC[i]; }
        g_cls_S[blockIdx.x] = a; g_cls_C[blockIdx.x] = c;
    }
}

// ======================= wmma bf16 GEMM + masked exp-sum (3-stage, KCH=64) =======================
// 128x128 tile per block; 8 warps in 4x2; warp tile 32x64 as 2x4 m16n16k16 frags.
// 3-stage cp.async pipeline, 64-wide k-chunks: 8 mainloop iterations with 2 full
// iterations of prefetch slack (~1200 cyc) to cover DRAM latency.
__global__ void __launch_bounds__(256, 2) k_gemm(const void* __restrict__ att,
                                                 const void* __restrict__ dtm) {
    extern __shared__ __nv_bfloat16 dyn[];   // NSTAGE stages of [A|B][128][KPAD]
    __shared__ float red[128][2];
    __shared__ unsigned char sdtm[128];

    int mode = mask_mode_of(att);
    int b = blockIdx.z, lt = blockIdx.y, tt = blockIdx.x;
    int tid = threadIdx.x;
    int wid = tid >> 5, lane = tid & 31;
    int wm = wid >> 1, wn = wid & 1;     // 4 x 2 warp grid

    if (tid < 128) sdtm[tid] = (unsigned char)mask_at(dtm, b * L2_ + L_ + tt * 128 + tid, mode);

    const __nv_bfloat16* A  = g_boxH + (size_t)(b * L_ + lt * 128) * D_;
    const __nv_bfloat16* Bt = g_tagH + (size_t)(b * L_ + tt * 128) * D_;

    wmma::fragment<wmma::accumulator, 16, 16, 16, float> acc[2][4];
    #pragma unroll
    for (int mi = 0; mi < 2; mi++)
        #pragma unroll
        for (int ni = 0; ni < 4; ni++)
            wmma::fill_fragment(acc[mi][ni], 0.0f);

    auto prefetch = [&](int s, int kc) {
        __nv_bfloat16* stA = dyn + s * STAGE_ELEMS;
        __nv_bfloat16* stB = stA + 128 * KPAD;
        #pragma unroll
        for (int it = 0; it < 4; it++) {
            int a = tid + it * 256;              // 0..1023
            int r = a >> 3, c8 = (a & 7) * 8;    // 8 chunks of 8 halfs per row
            __pipeline_memcpy_async(&stA[r * KPAD + c8], A + (size_t)r * D_ + kc + c8, 16);
        }
        #pragma unroll
        for (int it = 0; it < 4; it++) {
            int a = tid + it * 256;
            int r = a >> 3, c8 = (a & 7) * 8;
            __pipeline_memcpy_async(&stB[r * KPAD + c8], Bt + (size_t)r * D_ + kc + c8, 16);
        }
        __pipeline_commit();
    };

    const int NIT = D_ / KCH;            // 8
    prefetch(0, 0);
    prefetch(1, KCH);
    for (int i = 0; i < NIT; i++) {
        if (i + 2 < NIT) prefetch((i + 2) % NSTAGE, (i + 2) * KCH);
        int pend = NIT - 1 - i; if (pend > 2) pend = 2;
        __pipeline_wait_prior(pend);
        __syncthreads();
        __nv_bfloat16* stA = dyn + (i % NSTAGE) * STAGE_ELEMS;
        __nv_bfloat16* stB = stA + 128 * KPAD;
        #pragma unroll
        for (int kk = 0; kk < KCH; kk += 16) {
            wmma::fragment<wmma::matrix_a, 16, 16, 16, __nv_bfloat16, wmma::row_major> af[2];
            #pragma unroll
            for (int mi = 0; mi < 2; mi++)
                wmma::load_matrix_sync(af[mi], &stA[(wm * 32 + mi * 16) * KPAD + kk], KPAD);
            wmma::fragment<wmma::matrix_b, 16, 16, 16, __nv_bfloat16, wmma::col_major> bf[4];
            #pragma unroll
            for (int ni = 0; ni < 4; ni++)
                wmma::load_matrix_sync(bf[ni], &stB[(wn * 64 + ni * 16) * KPAD + kk], KPAD);
            #pragma unroll
            for (int mi = 0; mi < 2; mi++)
                #pragma unroll
                for (int ni = 0; ni < 4; ni++)
                    wmma::mma_sync(acc[mi][ni], af[mi], bf[ni], acc[mi][ni]);
        }
        __syncthreads();
    }

    // epilogue: masked exp + row reduce; per-warp fp32 scratch aliased onto dyn
    float* scr = (float*)dyn + wid * (16 * 20);   // 1280B/warp slice
    int r = lane & 15, h = lane >> 4;    // row within frag, column half
    #pragma unroll
    for (int mi = 0; mi < 2; mi++) {
        float rowsum = 0.f;
        #pragma unroll
        for (int ni = 0; ni < 4; ni++) {
            wmma::store_matrix_sync(scr, acc[mi][ni], 20, wmma::mem_row_major);
            __syncwarp();
            float s = 0.f;
            #pragma unroll
            for (int c = 0; c < 8; c++) {
                int col = h * 8 + c;
                int gc = wn * 64 + ni * 16 + col;
                if (sdtm[gc]) s += __expf(scr[r * 20 + col] * INV_TEMP);
            }
            rowsum += s;
            __syncwarp();
        }
        rowsum += __shfl_xor_sync(0xffffffffu, rowsum, 16);
        if (h == 0) red[wm * 32 + mi * 16 + r][wn] = rowsum;
    }
    __syncthreads();
    if (tid < 128) {
        float s = red[tid][0] + red[tid][1];
        g_den_part[(size_t)(b * L_ + lt * 128 + tid) * 8 + tt] = s;
    }
}

// ======================= pointer loss (targets + combine) =======================
__global__ void __launch_bounds__(256) k_ptr(const float* __restrict__ box,
                                             const float* __restrict__ tag,
                                             const int* __restrict__ bidx,
                                             const void* __restrict__ att,
                                             const void* __restrict__ dtm) {
    int mode = mask_mode_of(att);
    int warp = threadIdx.x >> 5, lane = threadIdx.x & 31;
    int gw = blockIdx.x * 8 + warp;          // gw = b*L + l
    int b = gw >> 10;
    float dv = (lane < 8) ? g_den_part[(size_t)gw * 8 + lane] : 0.f;
    #pragma unroll
    for (int o = 16; o; o >>= 1) dv += __shfl_xor_sync(0xffffffffu, dv, o);
    float logden = logf(dv + EPSF);
    const int* bi = bidx + (size_t)gw * K_;
    const float* brow = box + (size_t)gw * D_;
    float ts = 0.f, tc = 0.f;
    bool valid = true;
    for (int k = 0; k < K_; k++) {
        int idx = bi[k];
        if (idx < 0) valid = false;
        if (valid) {
            int rc = idx - L_;
            rc = rc < 0 ? 0 : (rc > L_ - 1 ? L_ - 1 : rc);
            if (mask_at(dtm, b * L2_ + L_ + rc, mode)) {
                const float* trow = tag + (size_t)(b * L_ + rc) * D_;
                float a = 0.f;
                #pragma unroll
                for (int i = 0; i < 16; i++) a += brow[lane + 32 * i] * trow[lane + 32 * i];
                #pragma unroll
                for (int o = 16; o; o >>= 1) a += __shfl_xor_sync(0xffffffffu, a, o);
                ts += logden - a * INV_TEMP;
                tc += 1.f;
            }
        }
    }
    __shared__ float sS[8], sC[8];
    if (lane == 0) { sS[warp] = ts; sC[warp] = tc; }
    __syncthreads();
    if (threadIdx.x == 0) {
        float s = 0.f, c = 0.f;
        #pragma unroll
        for (int i = 0; i < 8; i++) { s += sS[i]; c += sC[i]; }
        g_ptr_S[blockIdx.x] = s; g_ptr_C[blockIdx.x] = c;
    }
}

// ======================= span contrastive (warp-per-row, block-reduced output) =======================
__global__ void __launch_bounds__(256) k_contr(const float* __restrict__ rsim,
                                               const float* __restrict__ csim,
                                               const float* __restrict__ rco,
                                               const float* __restrict__ cco) {
    int warp = threadIdx.x >> 5, lane = threadIdx.x & 31;
    int row = blockIdx.x * 8 + warp;         // 0..16383
    int slot = row >> 13;
    int bi = row & 8191;
    int i = bi & 1023;                       // diagonal index
    const float* sim  = slot ? csim : rsim;
    const float* coef = slot ? cco : rco;
    const float4* s4 = (const float4*)(sim  + (size_t)bi * L_);
    const float4* c4 = (const float4*)(coef + (size_t)bi * L_);

    float s[32];
    float W = 0.f, WSr = 0.f, m = -1e30f;
    #pragma unroll
    for (int j = 0; j < 8; j++) {
        float4 sv = s4[lane + 32 * j];
        float4 cv = c4[lane + 32 * j];
        float a0 = sv.x * INV_TEMP, a1 = sv.y * INV_TEMP;
        float a2 = sv.z * INV_TEMP, a3 = sv.w * INV_TEMP;
        s[4 * j] = a0; s[4 * j + 1] = a1; s[4 * j + 2] = a2; s[4 * j + 3] = a3;
        m = fmaxf(m, fmaxf(fmaxf(a0, a1), fmaxf(a2, a3)));
        float w0 = fmaxf(cv.x, 0.f), w1 = fmaxf(cv.y, 0.f);
        float w2 = fmaxf(cv.z, 0.f), w3 = fmaxf(cv.w, 0.f);
        W += (w0 + w1) + (w2 + w3);
        WSr += w0 * a0 + w1 * a1 + w2 * a2 + w3 * a3;
    }
    #pragma unroll
    for (int o = 16; o; o >>= 1) m = fmaxf(m, __shfl_xor_sync(0xffffffffu, m, o));

    float es = 0.f, ed = 0.f;
    #pragma unroll
    for (int j = 0; j < 8; j++) {
        #pragma unroll
        for (int q = 0; q < 4; q++) {
            float e = __expf(s[4 * j + q] - m);   // arg <= 0 (max-subtracted)
            es += e;
            if (4 * lane + 128 * j + q == i) ed = e;
        }
    }
    #pragma unroll
    for (int o = 16; o; o >>= 1) {
        es  += __shfl_xor_sync(0xffffffffu, es, o);
        W   += __shfl_xor_sync(0xffffffffu, W, o);
        WSr += __shfl_xor_sync(0xffffffffu, WSr, o);
        ed  += __shfl_xor_sync(0xffffffffu, ed, o);
    }
    __shared__ float sL[8], sP[8];
    if (lane == 0) {
        float den = es - ed;
        float logden = logf(den + EPSF);
        float haspos = W > 0.f ? 1.f : 0.f;
        float WS = WSr - m * W;              // sum(w * (s - m))
        float loss = (logden * W - WS) / (W + EPSF);
        sL[warp] = haspos * loss;
        sP[warp] = haspos;
    }
    __syncthreads();
    if (threadIdx.x == 0) {
        float l = 0.f, p = 0.f;
        #pragma unroll
        for (int w = 0; w < 8; w++) { l += sL[w]; p += sP[w]; }
        g_con_L[blockIdx.x] = l;
        g_con_P[blockIdx.x] = p;
    }
}

// ======================= final deterministic combine =======================
// MLP-4 strided sum: 4 independent accumulators keep 4 loads in flight.
__device__ float blk_sum(const float* p, int n, volatile float* sh) {
    float a0 = 0.f, a1 = 0.f, a2 = 0.f, a3 = 0.f;
    int i = threadIdx.x;
    for (; i < n - 768; i += 1024) {
        a0 += p[i]; a1 += p[i + 256]; a2 += p[i + 512]; a3 += p[i + 768];
    }
    for (; i < n; i += 256) a0 += p[i];
    float a = (a0 + a1) + (a2 + a3);
    #pragma unroll
    for (int o = 16; o; o >>= 1) a += __shfl_xor_sync(0xffffffffu, a, o);
    __syncthreads();
    if ((threadIdx.x & 31) == 0) sh[threadIdx.x >> 5] = a;
    __syncthreads();
    if (threadIdx.x == 0) {
        float r = 0.f;
        for (int w = 0; w < 8; w++) r += sh[w];
        sh[8] = r;
    }
    __syncthreads();
    float r = sh[8];
    __syncthreads();
    return r;
}

__global__ void __launch_bounds__(256) k_final(float* __restrict__ out) {
    __shared__ float sh[16];
    float clsS = blk_sum(g_cls_S, 1024, sh);
    float clsC = blk_sum(g_cls_C, 1024, sh);
    float cls = clsS / fmaxf(clsC, 1.f);

    float emp = 0.f;
    for (int b = 0; b < B_; b++) {
        float S = blk_sum(g_emp_S + b * 128, 128, sh);
        float C = blk_sum(g_emp_C + b * 128, 128, sh);
        emp += S / fmaxf(C, 1.f);
    }
    emp *= (1.f / B_);

    float ptrS = blk_sum(g_ptr_S, 1024, sh);
    float ptrC = blk_sum(g_ptr_C, 1024, sh);
    float ptr = (ptrC > 0.f) ? ptrS / fmaxf(ptrC, 1.f) : 0.f;

    float rL = blk_sum(g_con_L, 1024, sh);
    float rP = blk_sum(g_con_P, 1024, sh);
    float row = (rP > 0.f) ? rL / fmaxf(rP, 1.f) : 0.f;

    float cL = blk_sum(g_con_L + 1024, 1024, sh);
    float cP = blk_sum(g_con_P + 1024, 1024, sh);
    float col = (cP > 0.f) ? cL / fmaxf(cP, 1.f) : 0.f;

    if (threadIdx.x == 0) {
        out[1] = cls; out[2] = ptr; out[3] = emp; out[4] = row; out[5] = col;
        out[0] = cls + ptr + emp + 0.5f * row + 0.5f * col;
    }
}

// ======================= launch =======================
extern "C" void kernel_launch(void* const* d_in, const int* in_sizes, int n_in,
                              void* d_out, int out_size) {
    (void)in_sizes; (void)n_in; (void)out_size;
    const int*           tok  = (const int*)d_in[0];            // token_ids (B,L)
    const int*           bidx = (const int*)d_in[1];            // box_indices (B,L,K)
    const void*          dtm  = d_in[2];                        // data_tag_mask (B,2L)
    const void*          att  = d_in[3];                        // attention_mask (B,2L)
    const float*         tlog = (const float*)d_in[4];          // tag_logits (B,L,V)
    const float*         boxp = (const float*)d_in[5];          // box_proj (B,L,D)
    const float*         tagp = (const float*)d_in[6];          // tag_proj (B,L,D)
    const float*         empp = (const float*)d_in[7];          // empty_proj (B,1,D)
    const float*         rsim = (const float*)d_in[8];
    const float*         csim = (const float*)d_in[9];
    const float*         rco  = (const float*)d_in[10];
    const float*         cco  = (const float*)d_in[11];
    float* out = (float*)d_out;

    static int inited = 0;
    static cudaStream_t s_side;
    static cudaEvent_t ev_fork, ev_join;
    if (!inited) {
        cudaFuncSetAttribute(k_gemm, cudaFuncAttributeMaxDynamicSharedMemorySize, GEMM_DYN_SMEM);
        cudaStreamCreateWithFlags(&s_side, cudaStreamNonBlocking);
        cudaEventCreateWithFlags(&ev_fork, cudaEventDisableTiming);
        cudaEventCreateWithFlags(&ev_join, cudaEventDisableTiming);
        inited = 1;
    }

    // fork: independent kernels (cls, contrastive) on the side stream
    cudaEventRecord(ev_fork, 0);
    cudaStreamWaitEvent(s_side, ev_fork, 0);
    k_cls<<<1024, 256, 0, s_side>>>(tlog, tok);
    k_contr<<<2048, 256, 0, s_side>>>(rsim, csim, rco, cco);
    cudaEventRecord(ev_join, s_side);

    // main chain: cvt(+empty BCE) -> gemm -> ptr
    k_cvt<<<2048, 256>>>(boxp, tagp, empp, att, dtm);
    dim3 gg(8, 8, B_);
    k_gemm<<<gg, 256, GEMM_DYN_SMEM>>>(att, dtm);
    k_ptr<<<1024, 256>>>(boxp, tagp, bidx, att, dtm);

    // join, then final combine
    cudaStreamWaitEvent(0, ev_join, 0);
    k_final<<<1, 256>>>(out);
}

// round 17
// speedup vs baseline: 1.0938x; 1.0085x over previous
#include <cuda_runtime.h>
#include <cuda_pipeline.h>
#include <cuda_bf16.h>
#include <math.h>
#include <stdint.h>
#include <mma.h>

using namespace nvcuda;

// Problem constants (fixed by the reference)
#define B_  8
#define L_  1024
#define D_  512
#define V_  64
#define K_  8
#define L2_ 2048            // masks are (B, 2L)
#define INV_TEMP 10.0f
#define EPSF 1e-10f
#define KCH 64              // k-chunk per pipeline stage (4 x k16 mma steps)
#define KPAD 72             // padded row stride in halfs (144 B)
#define NSTAGE 3
#define STAGE_ELEMS (2 * 128 * KPAD)              // bf16 elems per stage (A+B)
#define GEMM_DYN_SMEM (NSTAGE * STAGE_ELEMS * 2)  // 110592 bytes

// -------- deterministic scratch (device globals; no allocations) --------
__device__ __nv_bfloat16 g_boxH[B_ * L_ * D_];   // bf16 box_proj (8 MB)
__device__ __nv_bfloat16 g_tagH[B_ * L_ * D_];   // bf16 tag_proj (8 MB)
__device__ float g_den_part[B_ * L_ * 8];    // [b*L+l][t_tile(128-wide)] masked exp partial sums
__device__ float g_cls_S[1024];
__device__ float g_cls_C[1024];
__device__ float g_emp_S[1024];              // [b*128 + chunk]
__device__ float g_emp_C[1024];
__device__ float g_ptr_S[1024];
__device__ float g_ptr_C[1024];
__device__ float g_con_L[2048];              // per-block partials (blocks 0-1023: row, 1024-2047: col)
__device__ float g_con_P[2048];

// ---- inline mask-mode probe: attention_mask[:, :L] is guaranteed all-True ----
// word 0 of att: 1 -> int32 masks, 0x3F800000 -> float32, else packed bytes.
__device__ __forceinline__ int mask_mode_of(const void* att) {
    unsigned int w = *(const unsigned int*)att;
    if (w == 1u) return 1;
    if (w == 0x3F800000u) return 2;
    return 0;
}

__device__ __forceinline__ int mask_at(const void* p, int idx, int mode) {
    if (mode == 1) return ((const int*)p)[idx] != 0;
    if (mode == 2) return ((const float*)p)[idx] != 0.0f;
    return ((const unsigned char*)p)[idx] != 0;
}

// ======================= fp32 -> bf16 convert pass (+ fused empty-BCE) =======================
__global__ void __launch_bounds__(256) k_cvt(const float* __restrict__ boxp,
                                             const float* __restrict__ tagp,
                                             const float* __restrict__ emp,
                                             const void* __restrict__ att,
                                             const void* __restrict__ dtm) {
    int blk = blockIdx.x;
    if (blk < 1024) {
        size_t base = ((size_t)blk * 256 + threadIdx.x) * 16;
        const float4* s = (const float4*)(boxp + base);
        __nv_bfloat162* d = (__nv_bfloat162*)(g_boxH + base);
        float4 v0 = s[0], v1 = s[1], v2 = s[2], v3 = s[3];   // batch loads (MLP 4)
        d[0] = __floats2bfloat162_rn(v0.x, v0.y); d[1] = __floats2bfloat162_rn(v0.z, v0.w);
        d[2] = __floats2bfloat162_rn(v1.x, v1.y); d[3] = __floats2bfloat162_rn(v1.z, v1.w);
        d[4] = __floats2bfloat162_rn(v2.x, v2.y); d[5] = __floats2bfloat162_rn(v2.z, v2.w);
        d[6] = __floats2bfloat162_rn(v3.x, v3.y); d[7] = __floats2bfloat162_rn(v3.z, v3.w);
        return;
    }
    // tag half: 8 warps, warp per row (8 rows per block)
    int mode = mask_mode_of(att);
    int bt = blk - 1024;                     // 0..1023
    int warp = threadIdx.x >> 5, lane = threadIdx.x & 31;
    int row = bt * 8 + warp;                 // = b*L + t
    int b = row >> 10, t = row & 1023;
    const float4* tp4 = (const float4*)(tagp + (size_t)row * D_);
    const float4* ep4 = (const float4*)(emp + (size_t)b * D_);
    __nv_bfloat162* dp = (__nv_bfloat162*)(g_tagH + (size_t)row * D_);
    float acc = 0.f;
    #pragma unroll
    for (int i = 0; i < 4; i++) {
        int idx = lane + 32 * i;             // float4 index within row
        float4 v = tp4[idx];
        float4 e = ep4[idx];
        acc += v.x * e.x + v.y * e.y + v.z * e.z + v.w * e.w;
        dp[2 * idx]     = __floats2bfloat162_rn(v.x, v.y);
        dp[2 * idx + 1] = __floats2bfloat162_rn(v.z, v.w);
    }
    #pragma unroll
    for (int o = 16; o; o >>= 1) acc += __shfl_xor_sync(0xffffffffu, acc, o);
    int a = mask_at(att, b * L2_ + L_ + t, mode);
    int d = mask_at(dtm, b * L2_ + L_ + t, mode);
    float tgt = (a && !d) ? 1.f : 0.f;
    float el = acc;
    float bce = fmaxf(el, 0.f) + log1pf(__expf(-fabsf(el))) - el * tgt;
    __shared__ float sS[8], sC[8];
    if (lane == 0) { sS[warp] = a ? bce : 0.f; sC[warp] = (float)a; }
    __syncthreads();
    if (threadIdx.x == 0) {
        float s = 0.f, c = 0.f;
        #pragma unroll
        for (int i = 0; i < 8; i++) { s += sS[i]; c += sC[i]; }
        g_emp_S[bt] = s; g_emp_C[bt] = c;
    }
}

// ======================= cls loss =======================
__global__ void __launch_bounds__(256) k_cls(const float* __restrict__ logits,
                                             const int* __restrict__ tok) {
    int warp = threadIdx.x >> 5, lane = threadIdx.x & 31;
    int row = blockIdx.x * 8 + warp;
    const float* p = logits + (size_t)row * V_;
    float s0 = p[lane], s1 = p[lane + 32];
    float m = fmaxf(s0, s1);
    #pragma unroll
    for (int o = 16; o; o >>= 1) m = fmaxf(m, __shfl_xor_sync(0xffffffffu, m, o));
    float e = __expf(s0 - m) + __expf(s1 - m);
    float ss = s0 + s1;
    int t = tok[row];
    float st = (lane == t ? s0 : 0.f) + (lane + 32 == t ? s1 : 0.f);
    #pragma unroll
    for (int o = 16; o; o >>= 1) {
        e  += __shfl_xor_sync(0xffffffffu, e, o);
        ss += __shfl_xor_sync(0xffffffffu, ss, o);
        st += __shfl_xor_sync(0xffffffffu, st, o);
    }
    float lse = m + logf(e);
    float per = 0.9f * (lse - st) + 0.1f * (lse - ss * (1.0f / V_));
    float valid = (t > 3) ? 1.f : 0.f;   // SPECIAL_IDS = 0..3
    __shared__ float sS[8], sC[8];
    if (lane == 0) { sS[warp] = per * valid; sC[warp] = valid; }
    __syncthreads();
    if (threadIdx.x == 0) {
        float a = 0.f, c = 0.f;
        #pragma unroll
        for (int i = 0; i < 8; i++) { a += sS[i]; c += sC[i]; }
        g_cls_S[blockIdx.x] = a; g_cls_C[blockIdx.x] = c;
    }
}

// ======================= wmma bf16 GEMM + masked exp-sum (3-stage, 2 tiles/block) =======================
// grid (4, 8, B): blockIdx.x = tt-pair. Each block computes tt = 2*pair and 2*pair+1
// sequentially (same lt -> A tile streams warm from L2 on the second pass).
// 256 blocks <= 296 resident slots = single wave (vs 512 blocks = 1.73 ragged waves).
__global__ void __launch_bounds__(256, 2) k_gemm(const void* __restrict__ att,
                                                 const void* __restrict__ dtm) {
    extern __shared__ __nv_bfloat16 dyn[];   // NSTAGE stages of [A|B][128][KPAD]
    __shared__ float red[128][2];
    __shared__ unsigned char sdtm[128];

    int mode = mask_mode_of(att);
    int b = blockIdx.z, lt = blockIdx.y, pair = blockIdx.x;
    int tid = threadIdx.x;
    int wid = tid >> 5, lane = tid & 31;
    int wm = wid >> 1, wn = wid & 1;     // 4 x 2 warp grid

    const __nv_bfloat16* A = g_boxH + (size_t)(b * L_ + lt * 128) * D_;

    for (int half = 0; half < 2; half++) {
        int tt = pair * 2 + half;
        const __nv_bfloat16* Bt = g_tagH + (size_t)(b * L_ + tt * 128) * D_;

        if (half) __syncthreads();           // protect sdtm/dyn reuse across halves
        if (tid < 128) sdtm[tid] = (unsigned char)mask_at(dtm, b * L2_ + L_ + tt * 128 + tid, mode);

        wmma::fragment<wmma::accumulator, 16, 16, 16, float> acc[2][4];
        #pragma unroll
        for (int mi = 0; mi < 2; mi++)
            #pragma unroll
            for (int ni = 0; ni < 4; ni++)
                wmma::fill_fragment(acc[mi][ni], 0.0f);

        auto prefetch = [&](int s, int kc) {
            __nv_bfloat16* stA = dyn + s * STAGE_ELEMS;
            __nv_bfloat16* stB = stA + 128 * KPAD;
            #pragma unroll
            for (int it = 0; it < 4; it++) {
                int a = tid + it * 256;              // 0..1023
                int r = a >> 3, c8 = (a & 7) * 8;    // 8 chunks of 8 halfs per row
                __pipeline_memcpy_async(&stA[r * KPAD + c8], A + (size_t)r * D_ + kc + c8, 16);
            }
            #pragma unroll
            for (int it = 0; it < 4; it++) {
                int a = tid + it * 256;
                int r = a >> 3, c8 = (a & 7) * 8;
                __pipeline_memcpy_async(&stB[r * KPAD + c8], Bt + (size_t)r * D_ + kc + c8, 16);
            }
            __pipeline_commit();
        };

        const int NIT = D_ / KCH;            // 8
        prefetch(0, 0);
        prefetch(1, KCH);
        for (int i = 0; i < NIT; i++) {
            if (i + 2 < NIT) prefetch((i + 2) % NSTAGE, (i + 2) * KCH);
            int pend = NIT - 1 - i; if (pend > 2) pend = 2;
            __pipeline_wait_prior(pend);
            __syncthreads();
            __nv_bfloat16* stA = dyn + (i % NSTAGE) * STAGE_ELEMS;
            __nv_bfloat16* stB = stA + 128 * KPAD;
            #pragma unroll
            for (int kk = 0; kk < KCH; kk += 16) {
                wmma::fragment<wmma::matrix_a, 16, 16, 16, __nv_bfloat16, wmma::row_major> af[2];
                #pragma unroll
                for (int mi = 0; mi < 2; mi++)
                    wmma::load_matrix_sync(af[mi], &stA[(wm * 32 + mi * 16) * KPAD + kk], KPAD);
                wmma::fragment<wmma::matrix_b, 16, 16, 16, __nv_bfloat16, wmma::col_major> bf[4];
                #pragma unroll
                for (int ni = 0; ni < 4; ni++)
                    wmma::load_matrix_sync(bf[ni], &stB[(wn * 64 + ni * 16) * KPAD + kk], KPAD);
                #pragma unroll
                for (int mi = 0; mi < 2; mi++)
                    #pragma unroll
                    for (int ni = 0; ni < 4; ni++)
                        wmma::mma_sync(acc[mi][ni], af[mi], bf[ni], acc[mi][ni]);
            }
            __syncthreads();
        }

        // epilogue: masked exp + row reduce; per-warp fp32 scratch aliased onto dyn
        float* scr = (float*)dyn + wid * (16 * 20);   // 1280B/warp slice
        int r = lane & 15, h = lane >> 4;    // row within frag, column half
        #pragma unroll
        for (int mi = 0; mi < 2; mi++) {
            float rowsum = 0.f;
            #pragma unroll
            for (int ni = 0; ni < 4; ni++) {
                wmma::store_matrix_sync(scr, acc[mi][ni], 20, wmma::mem_row_major);
                __syncwarp();
                float s = 0.f;
                #pragma unroll
                for (int c = 0; c < 8; c++) {
                    int col = h * 8 + c;
                    int gc = wn * 64 + ni * 16 + col;
                    if (sdtm[gc]) s += __expf(scr[r * 20 + col] * INV_TEMP);
                }
                rowsum += s;
                __syncwarp();
            }
            rowsum += __shfl_xor_sync(0xffffffffu, rowsum, 16);
            if (h == 0) red[wm * 32 + mi * 16 + r][wn] = rowsum;
        }
        __syncthreads();
        if (tid < 128) {
            float s = red[tid][0] + red[tid][1];
            g_den_part[(size_t)(b * L_ + lt * 128 + tid) * 8 + tt] = s;
        }
    }
}

// ======================= pointer loss (targets + combine) =======================
__global__ void __launch_bounds__(256) k_ptr(const float* __restrict__ box,
                                             const float* __restrict__ tag,
                                             const int* __restrict__ bidx,
                                             const void* __restrict__ att,
                                             const void* __restrict__ dtm) {
    int mode = mask_mode_of(att);
    int warp = threadIdx.x >> 5, lane = threadIdx.x & 31;
    int gw = blockIdx.x * 8 + warp;          // gw = b*L + l
    int b = gw >> 10;
    float dv = (lane < 8) ? g_den_part[(size_t)gw * 8 + lane] : 0.f;
    #pragma unroll
    for (int o = 16; o; o >>= 1) dv += __shfl_xor_sync(0xffffffffu, dv, o);
    float logden = logf(dv + EPSF);
    const int* bi = bidx + (size_t)gw * K_;
    const float* brow = box + (size_t)gw * D_;
    float ts = 0.f, tc = 0.f;
    bool valid = true;
    for (int k = 0; k < K_; k++) {
        int idx = bi[k];
        if (idx < 0) valid = false;
        if (valid) {
            int rc = idx - L_;
            rc = rc < 0 ? 0 : (rc > L_ - 1 ? L_ - 1 : rc);
            if (mask_at(dtm, b * L2_ + L_ + rc, mode)) {
                const float* trow = tag + (size_t)(b * L_ + rc) * D_;
                float a = 0.f;
                #pragma unroll
                for (int i = 0; i < 16; i++) a += brow[lane + 32 * i] * trow[lane + 32 * i];
                #pragma unroll
                for (int o = 16; o; o >>= 1) a += __shfl_xor_sync(0xffffffffu, a, o);
                ts += logden - a * INV_TEMP;
                tc += 1.f;
            }
        }
    }
    __shared__ float sS[8], sC[8];
    if (lane == 0) { sS[warp] = ts; sC[warp] = tc; }
    __syncthreads();
    if (threadIdx.x == 0) {
        float s = 0.f, c = 0.f;
        #pragma unroll
        for (int i = 0; i < 8; i++) { s += sS[i]; c += sC[i]; }
        g_ptr_S[blockIdx.x] = s; g_ptr_C[blockIdx.x] = c;
    }
}

// ======================= span contrastive (warp-per-row, block-reduced output) =======================
__global__ void __launch_bounds__(256) k_contr(const float* __restrict__ rsim,
                                               const float* __restrict__ csim,
                                               const float* __restrict__ rco,
                                               const float* __restrict__ cco) {
    int warp = threadIdx.x >> 5, lane = threadIdx.x & 31;
    int row = blockIdx.x * 8 + warp;         // 0..16383
    int slot = row >> 13;
    int bi = row & 8191;
    int i = bi & 1023;                       // diagonal index
    const float* sim  = slot ? csim : rsim;
    const float* coef = slot ? cco : rco;
    const float4* s4 = (const float4*)(sim  + (size_t)bi * L_);
    const float4* c4 = (const float4*)(coef + (size_t)bi * L_);

    float s[32];
    float W = 0.f, WSr = 0.f, m = -1e30f;
    #pragma unroll
    for (int j = 0; j < 8; j++) {
        float4 sv = s4[lane + 32 * j];
        float4 cv = c4[lane + 32 * j];
        float a0 = sv.x * INV_TEMP, a1 = sv.y * INV_TEMP;
        float a2 = sv.z * INV_TEMP, a3 = sv.w * INV_TEMP;
        s[4 * j] = a0; s[4 * j + 1] = a1; s[4 * j + 2] = a2; s[4 * j + 3] = a3;
        m = fmaxf(m, fmaxf(fmaxf(a0, a1), fmaxf(a2, a3)));
        float w0 = fmaxf(cv.x, 0.f), w1 = fmaxf(cv.y, 0.f);
        float w2 = fmaxf(cv.z, 0.f), w3 = fmaxf(cv.w, 0.f);
        W += (w0 + w1) + (w2 + w3);
        WSr += w0 * a0 + w1 * a1 + w2 * a2 + w3 * a3;
    }
    #pragma unroll
    for (int o = 16; o; o >>= 1) m = fmaxf(m, __shfl_xor_sync(0xffffffffu, m, o));

    float es = 0.f, ed = 0.f;
    #pragma unroll
    for (int j = 0; j < 8; j++) {
        #pragma unroll
        for (int q = 0; q < 4; q++) {
            float e = __expf(s[4 * j + q] - m);   // arg <= 0 (max-subtracted)
            es += e;
            if (4 * lane + 128 * j + q == i) ed = e;
        }
    }
    #pragma unroll
    for (int o = 16; o; o >>= 1) {
        es  += __shfl_xor_sync(0xffffffffu, es, o);
        W   += __shfl_xor_sync(0xffffffffu, W, o);
        WSr += __shfl_xor_sync(0xffffffffu, WSr, o);
        ed  += __shfl_xor_sync(0xffffffffu, ed, o);
    }
    __shared__ float sL[8], sP[8];
    if (lane == 0) {
        float den = es - ed;
        float logden = logf(den + EPSF);
        float haspos = W > 0.f ? 1.f : 0.f;
        float WS = WSr - m * W;              // sum(w * (s - m))
        float loss = (logden * W - WS) / (W + EPSF);
        sL[warp] = haspos * loss;
        sP[warp] = haspos;
    }
    __syncthreads();
    if (threadIdx.x == 0) {
        float l = 0.f, p = 0.f;
        #pragma unroll
        for (int w = 0; w < 8; w++) { l += sL[w]; p += sP[w]; }
        g_con_L[blockIdx.x] = l;
        g_con_P[blockIdx.x] = p;
    }
}

// ======================= final deterministic combine =======================
// MLP-4 strided sum: 4 independent accumulators keep 4 loads in flight.
__device__ float blk_sum(const float* p, int n, volatile float* sh) {
    float a0 = 0.f, a1 = 0.f, a2 = 0.f, a3 = 0.f;
    int i = threadIdx.x;
    for (; i < n - 768; i += 1024) {
        a0 += p[i]; a1 += p[i + 256]; a2 += p[i + 512]; a3 += p[i + 768];
    }
    for (; i < n; i += 256) a0 += p[i];
    float a = (a0 + a1) + (a2 + a3);
    #pragma unroll
    for (int o = 16; o; o >>= 1) a += __shfl_xor_sync(0xffffffffu, a, o);
    __syncthreads();
    if ((threadIdx.x & 31) == 0) sh[threadIdx.x >> 5] = a;
    __syncthreads();
    if (threadIdx.x == 0) {
        float r = 0.f;
        for (int w = 0; w < 8; w++) r += sh[w];
        sh[8] = r;
    }
    __syncthreads();
    float r = sh[8];
    __syncthreads();
    return r;
}

__global__ void __launch_bounds__(256) k_final(float* __restrict__ out) {
    __shared__ float sh[16];
    float clsS = blk_sum(g_cls_S, 1024, sh);
    float clsC = blk_sum(g_cls_C, 1024, sh);
    float cls = clsS / fmaxf(clsC, 1.f);

    float emp = 0.f;
    for (int b = 0; b < B_; b++) {
        float S = blk_sum(g_emp_S + b * 128, 128, sh);
        float C = blk_sum(g_emp_C + b * 128, 128, sh);
        emp += S / fmaxf(C, 1.f);
    }
    emp *= (1.f / B_);

    float ptrS = blk_sum(g_ptr_S, 1024, sh);
    float ptrC = blk_sum(g_ptr_C, 1024, sh);
    float ptr = (ptrC > 0.f) ? ptrS / fmaxf(ptrC, 1.f) : 0.f;

    float rL = blk_sum(g_con_L, 1024, sh);
    float rP = blk_sum(g_con_P, 1024, sh);
    float row = (rP > 0.f) ? rL / fmaxf(rP, 1.f) : 0.f;

    float cL = blk_sum(g_con_L + 1024, 1024, sh);
    float cP = blk_sum(g_con_P + 1024, 1024, sh);
    float col = (cP > 0.f) ? cL / fmaxf(cP, 1.f) : 0.f;

    if (threadIdx.x == 0) {
        out[1] = cls; out[2] = ptr; out[3] = emp; out[4] = row; out[5] = col;
        out[0] = cls + ptr + emp + 0.5f * row + 0.5f * col;
    }
}

// ======================= launch =======================
extern "C" void kernel_launch(void* const* d_in, const int* in_sizes, int n_in,
                              void* d_out, int out_size) {
    (void)in_sizes; (void)n_in; (void)out_size;
    const int*           tok  = (const int*)d_in[0];            // token_ids (B,L)
    const int*           bidx = (const int*)d_in[1];            // box_indices (B,L,K)
    const void*          dtm  = d_in[2];                        // data_tag_mask (B,2L)
    const void*          att  = d_in[3];                        // attention_mask (B,2L)
    const float*         tlog = (const float*)d_in[4];          // tag_logits (B,L,V)
    const float*         boxp = (const float*)d_in[5];          // box_proj (B,L,D)
    const float*         tagp = (const float*)d_in[6];          // tag_proj (B,L,D)
    const float*         empp = (const float*)d_in[7];          // empty_proj (B,1,D)
    const float*         rsim = (const float*)d_in[8];
    const float*         csim = (const float*)d_in[9];
    const float*         rco  = (const float*)d_in[10];
    const float*         cco  = (const float*)d_in[11];
    float* out = (float*)d_out;

    static int inited = 0;
    static cudaStream_t s_side;
    static cudaEvent_t ev_fork, ev_join;
    if (!inited) {
        cudaFuncSetAttribute(k_gemm, cudaFuncAttributeMaxDynamicSharedMemorySize, GEMM_DYN_SMEM);
        cudaStreamCreateWithFlags(&s_side, cudaStreamNonBlocking);
        cudaEventCreateWithFlags(&ev_fork, cudaEventDisableTiming);
        cudaEventCreateWithFlags(&ev_join, cudaEventDisableTiming);
        inited = 1;
    }

    // fork: independent kernels (cls, contrastive) on the side stream
    cudaEventRecord(ev_fork, 0);
    cudaStreamWaitEvent(s_side, ev_fork, 0);
    k_cls<<<1024, 256, 0, s_side>>>(tlog, tok);
    k_contr<<<2048, 256, 0, s_side>>>(rsim, csim, rco, cco);
    cudaEventRecord(ev_join, s_side);

    // main chain: cvt(+empty BCE) -> gemm -> ptr
    k_cvt<<<2048, 256>>>(boxp, tagp, empp, att, dtm);
    dim3 gg(4, 8, B_);
    k_gemm<<<gg, 256, GEMM_DYN_SMEM>>>(att, dtm);
    k_ptr<<<1024, 256>>>(boxp, tagp, bidx, att, dtm);

    // join, then final combine
    cudaStreamWaitEvent(0, ev_join, 0);
    k_final<<<1, 256>>>(out);
}